// round 15
// baseline (speedup 1.0000x reference)
#include <cuda_runtime.h>
#include <cuda_fp16.h>
#include <cstdint>

#define NSEQ 2048
#define DDIM 1024
#define BATCH 8
#define TWO_N (2*NSEQ)
#define MTOT (BATCH*NSEQ)          // 16384 flat rows

// ------------------------- scratch (__device__ globals) ---------------------
__device__ __half g_xh [(size_t)MTOT*DDIM];
__device__ __half g_wth[3*(size_t)DDIM*DDIM];   // W^T hi, [which][dout][din]
__device__ __half g_qh [(size_t)MTOT*DDIM];      // q hi only
__device__ __half g_kh [(size_t)MTOT*DDIM];      // k hi only
__device__ __half g_vth[(size_t)BATCH*DDIM*NSEQ];// v^T hi only [b][e][m]
__device__ float  g_s  [(size_t)BATCH*NSEQ*NSEQ];// scores fp32
__device__ __half g_ah [(size_t)BATCH*NSEQ*NSEQ];// softmax hi only
__device__ float  g_c  [TWO_N];

// ------------------------------ PTX helpers --------------------------------
__device__ __forceinline__ uint32_t smem_u32(const void* p) {
    uint32_t a;
    asm("{ .reg .u64 t; cvta.to.shared.u64 t, %1; cvt.u32.u64 %0, t; }" : "=r"(a) : "l"(p));
    return a;
}
__device__ __forceinline__ void cp_async16(uint32_t dst, const void* src) {
    asm volatile("cp.async.cg.shared.global [%0], [%1], 16;" :: "r"(dst), "l"(src));
}
#define CP_COMMIT() asm volatile("cp.async.commit_group;")

__device__ __forceinline__ void ldsm4(uint32_t (&r)[4], uint32_t addr) {
    asm volatile("ldmatrix.sync.aligned.m8n8.x4.shared.b16 {%0,%1,%2,%3}, [%4];"
        : "=r"(r[0]), "=r"(r[1]), "=r"(r[2]), "=r"(r[3]) : "r"(addr));
}
__device__ __forceinline__ void mma16816(float (&c)[4], const uint32_t (&a)[4],
                                         uint32_t b0, uint32_t b1) {
    asm volatile("mma.sync.aligned.m16n8k16.row.col.f32.f16.f16.f32 "
        "{%0,%1,%2,%3}, {%4,%5,%6,%7}, {%8,%9}, {%0,%1,%2,%3};"
        : "+f"(c[0]), "+f"(c[1]), "+f"(c[2]), "+f"(c[3])
        : "r"(a[0]), "r"(a[1]), "r"(a[2]), "r"(a[3]), "r"(b0), "r"(b1));
}

// ---------------------- GEMM core -------------------------------------------
// C[128 x 256] = A[rowTile..+128][:K] * B[colTile..+256][:K]^T
// A,B row-major fp16, row stride K. BK=64 (128B rows, XOR-swizzled), 3 stages.
// 512 threads, 16 warps: warp grid 4(M) x 4(N), warp tile 32x64 via 2x8 m16n8k16.
#define NTHREADS 512
#define STAGES 3
#define TILEA  (128*128)              // 16384 B (A: 128 rows x 128B)
#define TILEBB (256*128)              // 32768 B (B: 256 rows x 128B)
#define STAGEB (TILEA+TILEBB)         // 49152 B
#define SMEMB  (STAGES*STAGEB)        // 147456 B

// physical smem offset for (row, 16B-seg) with bank swizzle
#define SWZ(row, seg) ((row) * 128 + ((((seg) ^ ((row) & 7))) << 4))

__device__ __forceinline__ void gemm_mma(
    const __half* A, const __half* B,
    int K, size_t rowTile, size_t colTile, uint32_t sbase, float acc[2][8][4])
{
    const int tid  = threadIdx.x;
    const int lane = tid & 31;
    const int warp = tid >> 5;
    const int wm = warp & 3;          // M offset wm*32
    const int wn = warp >> 2;         // N offset wn*64 (0..3)
    const int NIT = K >> 6;           // 64-wide k chunks

#pragma unroll
    for (int im = 0; im < 2; im++)
#pragma unroll
        for (int in = 0; in < 8; in++)
#pragma unroll
            for (int j = 0; j < 4; j++) acc[im][in][j] = 0.f;

    auto issue = [&](int j) {
        int kb = j << 6;
        uint32_t sA = sbase + (j % STAGES) * STAGEB;
        uint32_t sB = sA + TILEA;
#pragma unroll
        for (int i = 0; i < 2; i++) {                 // A: 1024 cp16
            int c = tid + NTHREADS * i;
            int row = c >> 3, seg = c & 7;
            cp_async16(sA + SWZ(row, seg),
                       A + (rowTile + row) * (size_t)K + kb + seg * 8);
        }
#pragma unroll
        for (int i = 0; i < 4; i++) {                 // B: 2048 cp16
            int c = tid + NTHREADS * i;
            int row = c >> 3, seg = c & 7;
            cp_async16(sB + SWZ(row, seg),
                       B + (colTile + row) * (size_t)K + kb + seg * 8);
        }
        CP_COMMIT();
    };

    issue(0); issue(1);

    // ldmatrix lane decomposition (g = lane>>3)
    const uint32_t rm    = lane & 7;
    const uint32_t aRow0 = (uint32_t)(wm * 32 + ((lane >> 3) & 1) * 8 + rm) * 128;
    const uint32_t aColg = (uint32_t)(lane >> 4);          // g>>1
    const uint32_t bRow0 = (uint32_t)(wn * 64 + (lane >> 4) * 8 + rm) * 128;
    const uint32_t bColg = (uint32_t)((lane >> 3) & 1);    // g&1

    for (int it = 0; it < NIT; it++) {
        if (it + 1 < NIT) asm volatile("cp.async.wait_group 1;" ::: "memory");
        else              asm volatile("cp.async.wait_group 0;" ::: "memory");
        __syncthreads();
        if (it + 2 < NIT) issue(it + 2);

        uint32_t sA = sbase + (it % STAGES) * STAGEB;
        uint32_t sB = sA + TILEA;
#pragma unroll
        for (int ks = 0; ks < 4; ks++) {       // four k16 steps per 64-chunk
            uint32_t aC = (((uint32_t)(ks * 2) + aColg) ^ rm) << 4;
            uint32_t bC = (((uint32_t)(ks * 2) + bColg) ^ rm) << 4;
            uint32_t a0[4], a1[4], b[4][4];
            ldsm4(a0, sA + aRow0 + aC);
            ldsm4(a1, sA + aRow0 + 16 * 128 + aC);
#pragma unroll
            for (int inp = 0; inp < 4; inp++)
                ldsm4(b[inp], sB + bRow0 + inp * 16 * 128 + bC);
#pragma unroll
            for (int inp = 0; inp < 4; inp++) {
                mma16816(acc[0][inp * 2 + 0], a0, b[inp][0], b[inp][1]);
                mma16816(acc[1][inp * 2 + 0], a1, b[inp][0], b[inp][1]);
                mma16816(acc[0][inp * 2 + 1], a0, b[inp][2], b[inp][3]);
                mma16816(acc[1][inp * 2 + 1], a1, b[inp][2], b[inp][3]);
            }
        }
    }
}

// ---------------------- merged projection kernel (1-pass, hi-only) ----------
// grid (512, 1, 3): z=0 q, z=1 k (M=n-tile, N=d-tile); z=2 v (M=e-tile, N=n-tile)
__global__ __launch_bounds__(NTHREADS, 1) void k_proj(const float* __restrict__ tq,
                                                      const float* __restrict__ tk,
                                                      const float* __restrict__ tv)
{
    extern __shared__ char dsm[];
    uint32_t sbase = smem_u32(dsm);
    int z = blockIdx.z;
    size_t woff = (size_t)z * DDIM * DDIM;
    float acc[2][8][4];
    int lane = threadIdx.x & 31, warp = threadIdx.x >> 5;
    int wm = warp & 3, wn = warp >> 2;

    if (z == 2) {
        int bx = blockIdx.x & 7, by = blockIdx.x >> 3;   // e-tile(8) x n-tile(64)
        size_t rowTile = (size_t)bx * 128;               // e
        size_t colTile = (size_t)by * 256;               // flat n
        gemm_mma(g_wth + woff, g_xh, DDIM, rowTile, colTile, sbase, acc);

        float tau = tv[0];
#pragma unroll
        for (int im = 0; im < 2; im++)
#pragma unroll
            for (int in = 0; in < 8; in++) {
                size_t e0 = rowTile + wm * 32 + im * 16 + (lane >> 2);
                size_t nf = colTile + wn * 64 + in * 8 + (lane & 3) * 2;
                size_t b = nf >> 11, m = nf & (NSEQ - 1);
#pragma unroll
                for (int h = 0; h < 2; h++) {
                    size_t e = e0 + h * 8;
                    __half2 hv;
                    hv.x = __float2half_rn(acc[im][in][2 * h + 0] * tau);
                    hv.y = __float2half_rn(acc[im][in][2 * h + 1] * tau);
                    *(__half2*)&g_vth[(b * DDIM + e) * NSEQ + m] = hv;
                }
            }
    } else {
        int bx = blockIdx.x & 3, by = blockIdx.x >> 2;   // d-tile(4) x n-tile(128)
        size_t rowTile = (size_t)by * 128;               // flat n
        size_t colTile = (size_t)bx * 256;               // d
        gemm_mma(g_xh, g_wth + woff, DDIM, rowTile, colTile, sbase, acc);

        float tau = z ? tk[0] : tq[0];
        __half* O = z ? g_kh : g_qh;
#pragma unroll
        for (int im = 0; im < 2; im++)
#pragma unroll
            for (int in = 0; in < 8; in++) {
                size_t n0 = rowTile + wm * 32 + im * 16 + (lane >> 2);
                size_t d  = colTile + wn * 64 + in * 8 + (lane & 3) * 2;
#pragma unroll
                for (int h = 0; h < 2; h++) {
                    size_t n = n0 + h * 8;
                    __half2 hv;
                    hv.x = __float2half_rn(acc[im][in][2 * h + 0] * tau);
                    hv.y = __float2half_rn(acc[im][in][2 * h + 1] * tau);
                    *(__half2*)&O[n * DDIM + d] = hv;
                }
            }
    }
}

// ---------------------- kernel: scores (1-pass) -----------------------------
// C[n][m] = q_h[n]·k_h[m];  S[b][n][m] = C*scale + P[n][m] + c[(n-m)&4095]
__global__ __launch_bounds__(NTHREADS, 1) void k_scores(const float* __restrict__ P)
{
    extern __shared__ char dsm[];
    uint32_t sbase = smem_u32(dsm);
    int b = blockIdx.z;
    size_t rowTile = (size_t)b * NSEQ + blockIdx.y * 128;   // flat n into q
    size_t colTile = (size_t)b * NSEQ + blockIdx.x * 256;   // flat m into k

    float acc[2][8][4];
    gemm_mma(g_qh, g_kh, DDIM, rowTile, colTile, sbase, acc);

    const float scale = 0.03125f;
    float* S = g_s + (size_t)b * NSEQ * NSEQ;
    int lane = threadIdx.x & 31, warp = threadIdx.x >> 5;
    int wm = warp & 3, wn = warp >> 2;
#pragma unroll
    for (int im = 0; im < 2; im++)
#pragma unroll
        for (int in = 0; in < 8; in++) {
            int n0 = blockIdx.y * 128 + wm * 32 + im * 16 + (lane >> 2);
            int m  = blockIdx.x * 256 + wn * 64 + in * 8 + (lane & 3) * 2;
#pragma unroll
            for (int h = 0; h < 2; h++) {
                int n = n0 + h * 8;
                float2 pv = *(const float2*)&P[(size_t)n * NSEQ + m];
                float2 v;
                v.x = acc[im][in][2 * h + 0] * scale + pv.x + g_c[(n - m) & (TWO_N - 1)];
                v.y = acc[im][in][2 * h + 1] * scale + pv.y + g_c[(n - m - 1) & (TWO_N - 1)];
                *(float2*)&S[(size_t)n * NSEQ + m] = v;
            }
        }
}

// ---------------------- kernel: out = A_h @ v_h (1-pass) --------------------
__global__ __launch_bounds__(NTHREADS, 1) void k_out(float* __restrict__ O)
{
    extern __shared__ char dsm[];
    uint32_t sbase = smem_u32(dsm);
    int b = blockIdx.z;
    size_t rowTile = (size_t)b * NSEQ + blockIdx.y * 128;   // flat n into attn
    size_t colTile = (size_t)b * DDIM + blockIdx.x * 256;   // flat e into vT

    float acc[2][8][4];
    gemm_mma(g_ah, g_vth, NSEQ, rowTile, colTile, sbase, acc);

    int lane = threadIdx.x & 31, warp = threadIdx.x >> 5;
    int wm = warp & 3, wn = warp >> 2;
#pragma unroll
    for (int im = 0; im < 2; im++)
#pragma unroll
        for (int in = 0; in < 8; in++) {
            int n0 = blockIdx.y * 128 + wm * 32 + im * 16 + (lane >> 2);
            int e  = blockIdx.x * 256 + wn * 64 + in * 8 + (lane & 3) * 2;
#pragma unroll
            for (int h = 0; h < 2; h++) {
                int n = n0 + h * 8;
                float2 v = make_float2(acc[im][in][2 * h + 0], acc[im][in][2 * h + 1]);
                *(float2*)&O[((size_t)b * NSEQ + n) * DDIM + e] = v;
            }
        }
}

// ---------------------- merged prologue kernel ------------------------------
// blocks [0, NBX)            : x -> fp16 convert
// blocks [NBX, NBX+NBW)      : W transpose (hi only)
// blocks [NBX+NBW, +TWO_N)   : circulant bias column
#define NBX ((MTOT*DDIM)/1024)        // 16384
#define NBW (32*32*3)                 // 3072

__global__ __launch_bounds__(256) void k_prologue(
    const float* __restrict__ x,
    const float* __restrict__ Wq, const float* __restrict__ Wk,
    const float* __restrict__ Wv, const float* __restrict__ R)
{
    int blk = blockIdx.x;
    int tid = threadIdx.x;

    if (blk < NBX) {                         // ---- conv_x ----
        size_t i = (size_t)blk * 256 + tid;
        float4 v = ((const float4*)x)[i];
        __half2 h01, h23;
        h01.x = __float2half_rn(v.x); h01.y = __float2half_rn(v.y);
        h23.x = __float2half_rn(v.z); h23.y = __float2half_rn(v.w);
        *(__half2*)&g_xh[i * 4 + 0] = h01;
        *(__half2*)&g_xh[i * 4 + 2] = h23;
    } else if (blk < NBX + NBW) {            // ---- conv_wT ----
        int idx = blk - NBX;
        int z = idx / (32 * 32);
        int rem = idx % (32 * 32);
        const float* W = (z == 0) ? Wq : (z == 1) ? Wk : Wv;
        int bx = (rem % 32) * 32, by = (rem / 32) * 32;
        int tx = tid & 31, ty = tid >> 5;    // 32 x 8
        __shared__ float t[32][33];
#pragma unroll
        for (int i = 0; i < 4; i++)
            t[ty + i * 8][tx] = W[(size_t)(by + ty + i * 8) * DDIM + bx + tx];
        __syncthreads();
        size_t base = (size_t)z * DDIM * DDIM;
#pragma unroll
        for (int i = 0; i < 4; i++) {
            int d = bx + ty + i * 8, k = by + tx;
            g_wth[base + (size_t)d * DDIM + k] = __float2half_rn(t[tx][ty + i * 8]);
        }
    } else {                                 // ---- bias ----
        int t = blk - NBX - NBW;
        int lane = tid & 31, wid = tid >> 5;
        __shared__ float red[8];
        const float w = 6.283185307179586f / (float)TWO_N;
        float s = 0.f;
        for (int j = tid; j < TWO_N; j += 256)
            s += R[j] * cosf(w * (float)((j * t) & (TWO_N - 1)));
#pragma unroll
        for (int o = 16; o; o >>= 1) s += __shfl_xor_sync(0xFFFFFFFFu, s, o);
        if (lane == 0) red[wid] = s;
        __syncthreads();
        if (tid == 0) {
            float tot = 0.f;
#pragma unroll
            for (int i = 0; i < 8; i++) tot += red[i];
            g_c[t] = tot * (1.0f / (float)TWO_N);
        }
    }
}

// ---------------------- softmax (hi-only store) -----------------------------
__global__ __launch_bounds__(256) void softmax_kernel() {
    size_t row = blockIdx.x;
    float* p = g_s + row * NSEQ;
    __half* ah = g_ah + row * NSEQ;
    int t = threadIdx.x, lane = t & 31, wid = t >> 5;
    __shared__ float red[8];

    float x[8];
#pragma unroll
    for (int i = 0; i < 8; i++) x[i] = p[t + i * 256];
    float m = x[0];
#pragma unroll
    for (int i = 1; i < 8; i++) m = fmaxf(m, x[i]);
#pragma unroll
    for (int o = 16; o; o >>= 1) m = fmaxf(m, __shfl_xor_sync(0xFFFFFFFFu, m, o));
    if (lane == 0) red[wid] = m;
    __syncthreads();
    float bm = red[0];
#pragma unroll
    for (int i = 1; i < 8; i++) bm = fmaxf(bm, red[i]);
    __syncthreads();
    float s = 0.f;
#pragma unroll
    for (int i = 0; i < 8; i++) { x[i] = expf(x[i] - bm); s += x[i]; }
#pragma unroll
    for (int o = 16; o; o >>= 1) s += __shfl_xor_sync(0xFFFFFFFFu, s, o);
    if (lane == 0) red[wid] = s;
    __syncthreads();
    float tot = red[0];
#pragma unroll
    for (int i = 1; i < 8; i++) tot += red[i];
    float inv = 1.0f / tot;
#pragma unroll
    for (int i = 0; i < 8; i++)
        ah[t + i * 256] = __float2half_rn(x[i] * inv);
}

// ---------------------- launch ----------------------------------------------
extern "C" void kernel_launch(void* const* d_in, const int* in_sizes, int n_in,
                              void* d_out, int out_size)
{
    const float* x  = (const float*)d_in[0];
    const float* Wq = (const float*)d_in[1];
    const float* Wk = (const float*)d_in[2];
    const float* Wv = (const float*)d_in[3];
    const float* P  = (const float*)d_in[4];
    const float* R  = (const float*)d_in[5];
    const float* tq = (const float*)d_in[6];
    const float* tk = (const float*)d_in[7];
    const float* tv = (const float*)d_in[8];
    float* out = (float*)d_out;

    cudaFuncSetAttribute(k_proj,   cudaFuncAttributeMaxDynamicSharedMemorySize, SMEMB);
    cudaFuncSetAttribute(k_scores, cudaFuncAttributeMaxDynamicSharedMemorySize, SMEMB);
    cudaFuncSetAttribute(k_out,    cudaFuncAttributeMaxDynamicSharedMemorySize, SMEMB);

    k_prologue<<<NBX + NBW + TWO_N, 256>>>(x, Wq, Wk, Wv, R);
    k_proj  <<<dim3(512, 1, 3), NTHREADS, SMEMB>>>(tq, tk, tv);
    k_scores<<<dim3(NSEQ / 256, NSEQ / 128, BATCH), NTHREADS, SMEMB>>>(P);
    softmax_kernel<<<dim3(BATCH * NSEQ), 256>>>();
    k_out   <<<dim3(DDIM / 256, NSEQ / 128, BATCH), NTHREADS, SMEMB>>>(out);
}

// round 16
// speedup vs baseline: 1.0259x; 1.0259x over previous
#include <cuda_runtime.h>
#include <cuda_fp16.h>
#include <cstdint>

#define NSEQ 2048
#define DDIM 1024
#define BATCH 8
#define TWO_N (2*NSEQ)
#define MTOT (BATCH*NSEQ)          // 16384 flat rows

// ------------------------- scratch (__device__ globals) ---------------------
__device__ __half g_xh [(size_t)MTOT*DDIM];
__device__ __half g_wth[3*(size_t)DDIM*DDIM];   // W^T hi, [which][dout][din]
__device__ __half g_qh [(size_t)MTOT*DDIM];      // q hi only
__device__ __half g_kh [(size_t)MTOT*DDIM];      // k hi only
__device__ __half g_vth[(size_t)BATCH*DDIM*NSEQ];// v^T hi only [b][e][m]
__device__ float  g_s  [(size_t)BATCH*NSEQ*NSEQ];// scores fp32
__device__ __half g_ah [(size_t)BATCH*NSEQ*NSEQ];// softmax hi only
__device__ float  g_c  [TWO_N];

// ------------------------------ PTX helpers --------------------------------
__device__ __forceinline__ uint32_t smem_u32(const void* p) {
    uint32_t a;
    asm("{ .reg .u64 t; cvta.to.shared.u64 t, %1; cvt.u32.u64 %0, t; }" : "=r"(a) : "l"(p));
    return a;
}
__device__ __forceinline__ void cp_async16(uint32_t dst, const void* src) {
    asm volatile("cp.async.cg.shared.global [%0], [%1], 16;" :: "r"(dst), "l"(src));
}
#define CP_COMMIT() asm volatile("cp.async.commit_group;")

__device__ __forceinline__ void ldsm4(uint32_t (&r)[4], uint32_t addr) {
    asm volatile("ldmatrix.sync.aligned.m8n8.x4.shared.b16 {%0,%1,%2,%3}, [%4];"
        : "=r"(r[0]), "=r"(r[1]), "=r"(r[2]), "=r"(r[3]) : "r"(addr));
}
__device__ __forceinline__ void mma16816(float (&c)[4], const uint32_t (&a)[4],
                                         uint32_t b0, uint32_t b1) {
    asm volatile("mma.sync.aligned.m16n8k16.row.col.f32.f16.f16.f32 "
        "{%0,%1,%2,%3}, {%4,%5,%6,%7}, {%8,%9}, {%0,%1,%2,%3};"
        : "+f"(c[0]), "+f"(c[1]), "+f"(c[2]), "+f"(c[3])
        : "r"(a[0]), "r"(a[1]), "r"(a[2]), "r"(a[3]), "r"(b0), "r"(b1));
}

// ---------------------- GEMM core: T sequential N-tiles ---------------------
// For tile t in [0,T): C_t[128 x 128] = A[rowTile..+128][:K] * B[colTile0+t*128..][:K]^T
// One continuous cp.async pipeline across tiles; epi(t, acc) between tiles.
// 256 threads, 8 warps: warp grid 4(M) x 2(N), warp tile 32x64 via 2x8 m16n8k16.
#define STAGES 3
#define TILEB  (128*128)              // 16384 B per operand tile
#define STAGEB (2*TILEB)              // 32768 B (A + B)
#define SMEMB  (STAGES*STAGEB)        // 98304 B

// physical smem offset for (row, 16B-seg) with bank swizzle
#define SWZ(row, seg) ((row) * 128 + ((((seg) ^ ((row) & 7))) << 4))

template<int T, typename F>
__device__ __forceinline__ void gemm_mt(
    const __half* A, const __half* B, int K,
    size_t rowTile, size_t colTile0, uint32_t sbase, F epi)
{
    const int tid  = threadIdx.x;
    const int lane = tid & 31;
    const int warp = tid >> 5;
    const int wm = warp & 3;          // M offset wm*32
    const int wn = warp >> 2;         // N offset wn*64
    const int NIT = K >> 6;           // 64-wide k chunks per tile
    const int TOT = T * NIT;

    float acc[2][8][4];
#pragma unroll
    for (int im = 0; im < 2; im++)
#pragma unroll
        for (int in = 0; in < 8; in++)
#pragma unroll
            for (int j = 0; j < 4; j++) acc[im][in][j] = 0.f;

    auto issue = [&](int j) {
        int tile = j / NIT;
        int kb   = (j - tile * NIT) << 6;
        size_t bRow = colTile0 + (size_t)tile * 128;
        uint32_t sA = sbase + (j % STAGES) * STAGEB;
        uint32_t sB = sA + TILEB;
#pragma unroll
        for (int i = 0; i < 4; i++) {
            int c = tid + 256 * i;            // 0..1023
            int row = c >> 3, seg = c & 7;
            cp_async16(sA + SWZ(row, seg),
                       A + (rowTile + row) * (size_t)K + kb + seg * 8);
        }
#pragma unroll
        for (int i = 0; i < 4; i++) {
            int c = tid + 256 * i;
            int row = c >> 3, seg = c & 7;
            cp_async16(sB + SWZ(row, seg),
                       B + (bRow + row) * (size_t)K + kb + seg * 8);
        }
        CP_COMMIT();
    };

    issue(0); issue(1);

    // ldmatrix lane decomposition (g = lane>>3)
    const uint32_t rm    = lane & 7;
    const uint32_t aRow0 = (uint32_t)(wm * 32 + ((lane >> 3) & 1) * 8 + rm) * 128;
    const uint32_t aColg = (uint32_t)(lane >> 4);          // g>>1
    const uint32_t bRow0 = (uint32_t)(wn * 64 + (lane >> 4) * 8 + rm) * 128;
    const uint32_t bColg = (uint32_t)((lane >> 3) & 1);    // g&1

    for (int it = 0; it < TOT; it++) {
        if (it + 1 < TOT) asm volatile("cp.async.wait_group 1;" ::: "memory");
        else              asm volatile("cp.async.wait_group 0;" ::: "memory");
        __syncthreads();
        if (it + 2 < TOT) issue(it + 2);

        uint32_t sA = sbase + (it % STAGES) * STAGEB;
        uint32_t sB = sA + TILEB;
#pragma unroll
        for (int ks = 0; ks < 4; ks++) {       // four k16 steps per 64-chunk
            uint32_t aC = (((uint32_t)(ks * 2) + aColg) ^ rm) << 4;
            uint32_t bC = (((uint32_t)(ks * 2) + bColg) ^ rm) << 4;
            uint32_t a0[4], a1[4], b[4][4];
            ldsm4(a0, sA + aRow0 + aC);
            ldsm4(a1, sA + aRow0 + 16 * 128 + aC);
#pragma unroll
            for (int inp = 0; inp < 4; inp++)
                ldsm4(b[inp], sB + bRow0 + inp * 16 * 128 + bC);
#pragma unroll
            for (int inp = 0; inp < 4; inp++) {
                mma16816(acc[0][inp * 2 + 0], a0, b[inp][0], b[inp][1]);
                mma16816(acc[1][inp * 2 + 0], a1, b[inp][0], b[inp][1]);
                mma16816(acc[0][inp * 2 + 1], a0, b[inp][2], b[inp][3]);
                mma16816(acc[1][inp * 2 + 1], a1, b[inp][2], b[inp][3]);
            }
        }

        if (((it + 1) % NIT) == 0) {          // tile boundary: flush acc
            epi(it / NIT, acc);
#pragma unroll
            for (int im = 0; im < 2; im++)
#pragma unroll
                for (int in = 0; in < 8; in++)
#pragma unroll
                    for (int j = 0; j < 4; j++) acc[im][in][j] = 0.f;
        }
    }
}

// ---------------------- merged projection kernel (1-pass, hi-only, T=2) -----
// grid (512, 1, 3):
//  z=0/1: bx=blockIdx.x&3 (pair of d-tiles), by=blockIdx.x>>2 (n-tile)
//  z=2:   bx=blockIdx.x&7 (e-tile),          by=blockIdx.x>>3 (pair of n-tiles)
__global__ __launch_bounds__(256, 2) void k_proj(const float* __restrict__ tq,
                                                 const float* __restrict__ tk,
                                                 const float* __restrict__ tv)
{
    extern __shared__ char dsm[];
    uint32_t sbase = smem_u32(dsm);
    int z = blockIdx.z;
    size_t woff = (size_t)z * DDIM * DDIM;
    int lane = threadIdx.x & 31, warp = threadIdx.x >> 5;
    int wm = warp & 3, wn = warp >> 2;

    if (z == 2) {
        int bx = blockIdx.x & 7, by = blockIdx.x >> 3;
        size_t rowTile = (size_t)bx * 128;                 // e
        size_t colTile0 = (size_t)by * 256;                // flat n (2 tiles)
        float tau = tv[0];
        gemm_mt<2>(g_wth + woff, g_xh, DDIM, rowTile, colTile0, sbase,
            [&](int tile, float (&acc)[2][8][4]) {
#pragma unroll
                for (int im = 0; im < 2; im++)
#pragma unroll
                    for (int in = 0; in < 8; in++) {
                        size_t e0 = rowTile + wm * 32 + im * 16 + (lane >> 2);
                        size_t nf = colTile0 + tile * 128 + wn * 64 + in * 8 + (lane & 3) * 2;
                        size_t b = nf >> 11, m = nf & (NSEQ - 1);
#pragma unroll
                        for (int h = 0; h < 2; h++) {
                            size_t e = e0 + h * 8;
                            __half2 hv;
                            hv.x = __float2half_rn(acc[im][in][2 * h + 0] * tau);
                            hv.y = __float2half_rn(acc[im][in][2 * h + 1] * tau);
                            *(__half2*)&g_vth[(b * DDIM + e) * NSEQ + m] = hv;
                        }
                    }
            });
    } else {
        int bx = blockIdx.x & 3, by = blockIdx.x >> 2;
        size_t rowTile = (size_t)by * 128;                 // flat n
        size_t colTile0 = (size_t)bx * 256;                // d (2 tiles)
        float tau = z ? tk[0] : tq[0];
        __half* O = z ? g_kh : g_qh;
        gemm_mt<2>(g_xh, g_wth + woff, DDIM, rowTile, colTile0, sbase,
            [&](int tile, float (&acc)[2][8][4]) {
#pragma unroll
                for (int im = 0; im < 2; im++)
#pragma unroll
                    for (int in = 0; in < 8; in++) {
                        size_t n0 = rowTile + wm * 32 + im * 16 + (lane >> 2);
                        size_t d  = colTile0 + tile * 128 + wn * 64 + in * 8 + (lane & 3) * 2;
#pragma unroll
                        for (int h = 0; h < 2; h++) {
                            size_t n = n0 + h * 8;
                            __half2 hv;
                            hv.x = __float2half_rn(acc[im][in][2 * h + 0] * tau);
                            hv.y = __float2half_rn(acc[im][in][2 * h + 1] * tau);
                            *(__half2*)&O[n * DDIM + d] = hv;
                        }
                    }
            });
    }
}

// ---------------------- kernel: scores (1-pass, T=2) ------------------------
// grid (8, 16, 8): x = pair of m-tiles, y = n-tile, z = batch
__global__ __launch_bounds__(256, 2) void k_scores(const float* __restrict__ P)
{
    extern __shared__ char dsm[];
    uint32_t sbase = smem_u32(dsm);
    int b = blockIdx.z;
    size_t rowTile  = (size_t)b * NSEQ + blockIdx.y * 128;   // flat n into q
    size_t colTile0 = (size_t)b * NSEQ + blockIdx.x * 256;   // flat m into k

    const float scale = 0.03125f;
    float* S = g_s + (size_t)b * NSEQ * NSEQ;
    int lane = threadIdx.x & 31, warp = threadIdx.x >> 5;
    int wm = warp & 3, wn = warp >> 2;

    gemm_mt<2>(g_qh, g_kh, DDIM, rowTile, colTile0, sbase,
        [&](int tile, float (&acc)[2][8][4]) {
#pragma unroll
            for (int im = 0; im < 2; im++)
#pragma unroll
                for (int in = 0; in < 8; in++) {
                    int n0 = blockIdx.y * 128 + wm * 32 + im * 16 + (lane >> 2);
                    int m  = blockIdx.x * 256 + tile * 128 + wn * 64 + in * 8 + (lane & 3) * 2;
#pragma unroll
                    for (int h = 0; h < 2; h++) {
                        int n = n0 + h * 8;
                        float2 pv = *(const float2*)&P[(size_t)n * NSEQ + m];
                        float2 v;
                        v.x = acc[im][in][2 * h + 0] * scale + pv.x + g_c[(n - m) & (TWO_N - 1)];
                        v.y = acc[im][in][2 * h + 1] * scale + pv.y + g_c[(n - m - 1) & (TWO_N - 1)];
                        *(float2*)&S[(size_t)n * NSEQ + m] = v;
                    }
                }
        });
}

// ---------------------- kernel: out = A_h @ v_h (1-pass, T=2) ---------------
// grid (4, 16, 8): x = pair of e-tiles, y = n-tile, z = batch
__global__ __launch_bounds__(256, 2) void k_out(float* __restrict__ O)
{
    extern __shared__ char dsm[];
    uint32_t sbase = smem_u32(dsm);
    int b = blockIdx.z;
    size_t rowTile  = (size_t)b * NSEQ + blockIdx.y * 128;   // flat n into attn
    size_t colTile0 = (size_t)b * DDIM + blockIdx.x * 256;   // flat e into vT

    int lane = threadIdx.x & 31, warp = threadIdx.x >> 5;
    int wm = warp & 3, wn = warp >> 2;

    gemm_mt<2>(g_ah, g_vth, NSEQ, rowTile, colTile0, sbase,
        [&](int tile, float (&acc)[2][8][4]) {
#pragma unroll
            for (int im = 0; im < 2; im++)
#pragma unroll
                for (int in = 0; in < 8; in++) {
                    int n0 = blockIdx.y * 128 + wm * 32 + im * 16 + (lane >> 2);
                    int e  = blockIdx.x * 256 + tile * 128 + wn * 64 + in * 8 + (lane & 3) * 2;
#pragma unroll
                    for (int h = 0; h < 2; h++) {
                        int n = n0 + h * 8;
                        float2 v = make_float2(acc[im][in][2 * h + 0], acc[im][in][2 * h + 1]);
                        *(float2*)&O[((size_t)b * NSEQ + n) * DDIM + e] = v;
                    }
                }
        });
}

// ---------------------- merged prologue kernel ------------------------------
// blocks [0, NBX)            : x -> fp16 convert
// blocks [NBX, NBX+NBW)      : W transpose (hi only)
// blocks [NBX+NBW, +TWO_N)   : circulant bias column
#define NBX ((MTOT*DDIM)/1024)        // 16384
#define NBW (32*32*3)                 // 3072

__global__ __launch_bounds__(256) void k_prologue(
    const float* __restrict__ x,
    const float* __restrict__ Wq, const float* __restrict__ Wk,
    const float* __restrict__ Wv, const float* __restrict__ R)
{
    int blk = blockIdx.x;
    int tid = threadIdx.x;

    if (blk < NBX) {                         // ---- conv_x ----
        size_t i = (size_t)blk * 256 + tid;
        float4 v = ((const float4*)x)[i];
        __half2 h01, h23;
        h01.x = __float2half_rn(v.x); h01.y = __float2half_rn(v.y);
        h23.x = __float2half_rn(v.z); h23.y = __float2half_rn(v.w);
        *(__half2*)&g_xh[i * 4 + 0] = h01;
        *(__half2*)&g_xh[i * 4 + 2] = h23;
    } else if (blk < NBX + NBW) {            // ---- conv_wT ----
        int idx = blk - NBX;
        int z = idx / (32 * 32);
        int rem = idx % (32 * 32);
        const float* W = (z == 0) ? Wq : (z == 1) ? Wk : Wv;
        int bx = (rem % 32) * 32, by = (rem / 32) * 32;
        int tx = tid & 31, ty = tid >> 5;    // 32 x 8
        __shared__ float t[32][33];
#pragma unroll
        for (int i = 0; i < 4; i++)
            t[ty + i * 8][tx] = W[(size_t)(by + ty + i * 8) * DDIM + bx + tx];
        __syncthreads();
        size_t base = (size_t)z * DDIM * DDIM;
#pragma unroll
        for (int i = 0; i < 4; i++) {
            int d = bx + ty + i * 8, k = by + tx;
            g_wth[base + (size_t)d * DDIM + k] = __float2half_rn(t[tx][ty + i * 8]);
        }
    } else {                                 // ---- bias ----
        int t = blk - NBX - NBW;
        int lane = tid & 31, wid = tid >> 5;
        __shared__ float red[8];
        const float w = 6.283185307179586f / (float)TWO_N;
        float s = 0.f;
        for (int j = tid; j < TWO_N; j += 256)
            s += R[j] * cosf(w * (float)((j * t) & (TWO_N - 1)));
#pragma unroll
        for (int o = 16; o; o >>= 1) s += __shfl_xor_sync(0xFFFFFFFFu, s, o);
        if (lane == 0) red[wid] = s;
        __syncthreads();
        if (tid == 0) {
            float tot = 0.f;
#pragma unroll
            for (int i = 0; i < 8; i++) tot += red[i];
            g_c[t] = tot * (1.0f / (float)TWO_N);
        }
    }
}

// ---------------------- softmax (hi-only store) -----------------------------
__global__ __launch_bounds__(256) void softmax_kernel() {
    size_t row = blockIdx.x;
    float* p = g_s + row * NSEQ;
    __half* ah = g_ah + row * NSEQ;
    int t = threadIdx.x, lane = t & 31, wid = t >> 5;
    __shared__ float red[8];

    float x[8];
#pragma unroll
    for (int i = 0; i < 8; i++) x[i] = p[t + i * 256];
    float m = x[0];
#pragma unroll
    for (int i = 1; i < 8; i++) m = fmaxf(m, x[i]);
#pragma unroll
    for (int o = 16; o; o >>= 1) m = fmaxf(m, __shfl_xor_sync(0xFFFFFFFFu, m, o));
    if (lane == 0) red[wid] = m;
    __syncthreads();
    float bm = red[0];
#pragma unroll
    for (int i = 1; i < 8; i++) bm = fmaxf(bm, red[i]);
    __syncthreads();
    float s = 0.f;
#pragma unroll
    for (int i = 0; i < 8; i++) { x[i] = expf(x[i] - bm); s += x[i]; }
#pragma unroll
    for (int o = 16; o; o >>= 1) s += __shfl_xor_sync(0xFFFFFFFFu, s, o);
    if (lane == 0) red[wid] = s;
    __syncthreads();
    float tot = red[0];
#pragma unroll
    for (int i = 1; i < 8; i++) tot += red[i];
    float inv = 1.0f / tot;
#pragma unroll
    for (int i = 0; i < 8; i++)
        ah[t + i * 256] = __float2half_rn(x[i] * inv);
}

// ---------------------- launch ----------------------------------------------
extern "C" void kernel_launch(void* const* d_in, const int* in_sizes, int n_in,
                              void* d_out, int out_size)
{
    const float* x  = (const float*)d_in[0];
    const float* Wq = (const float*)d_in[1];
    const float* Wk = (const float*)d_in[2];
    const float* Wv = (const float*)d_in[3];
    const float* P  = (const float*)d_in[4];
    const float* R  = (const float*)d_in[5];
    const float* tq = (const float*)d_in[6];
    const float* tk = (const float*)d_in[7];
    const float* tv = (const float*)d_in[8];
    float* out = (float*)d_out;

    cudaFuncSetAttribute(k_proj,   cudaFuncAttributeMaxDynamicSharedMemorySize, SMEMB);
    cudaFuncSetAttribute(k_scores, cudaFuncAttributeMaxDynamicSharedMemorySize, SMEMB);
    cudaFuncSetAttribute(k_out,    cudaFuncAttributeMaxDynamicSharedMemorySize, SMEMB);

    k_prologue<<<NBX + NBW + TWO_N, 256>>>(x, Wq, Wk, Wv, R);
    k_proj  <<<dim3(512, 1, 3), 256, SMEMB>>>(tq, tk, tv);
    k_scores<<<dim3(NSEQ / 256, NSEQ / 128, BATCH), 256, SMEMB>>>(P);
    softmax_kernel<<<dim3(BATCH * NSEQ), 256>>>();
    k_out   <<<dim3(DDIM / 256, NSEQ / 128, BATCH), 256, SMEMB>>>(out);
}

// round 17
// speedup vs baseline: 1.1592x; 1.1300x over previous
#include <cuda_runtime.h>
#include <cuda_fp16.h>
#include <cstdint>

#define NSEQ 2048
#define DDIM 1024
#define BATCH 8
#define TWO_N (2*NSEQ)
#define MTOT (BATCH*NSEQ)          // 16384 flat rows

// ------------------------- scratch (__device__ globals) ---------------------
__device__ __half g_xh [(size_t)MTOT*DDIM];
__device__ __half g_wth[3*(size_t)DDIM*DDIM];   // W^T hi, [which][dout][din]
__device__ __half g_qh [(size_t)MTOT*DDIM];      // q hi only
__device__ __half g_kh [(size_t)MTOT*DDIM];      // k hi only
__device__ __half g_vth[(size_t)BATCH*DDIM*NSEQ];// v^T hi only [b][e][m]
__device__ float  g_s  [(size_t)BATCH*NSEQ*NSEQ];// scores fp32
__device__ __half g_ah [(size_t)BATCH*NSEQ*NSEQ];// softmax hi only
__device__ float  g_c  [TWO_N];

// ------------------------------ PTX helpers --------------------------------
__device__ __forceinline__ uint32_t smem_u32(const void* p) {
    uint32_t a;
    asm("{ .reg .u64 t; cvta.to.shared.u64 t, %1; cvt.u32.u64 %0, t; }" : "=r"(a) : "l"(p));
    return a;
}
__device__ __forceinline__ void cp_async16(uint32_t dst, const void* src) {
    asm volatile("cp.async.cg.shared.global [%0], [%1], 16;" :: "r"(dst), "l"(src));
}
#define CP_COMMIT() asm volatile("cp.async.commit_group;")

__device__ __forceinline__ void ldsm4(uint32_t (&r)[4], uint32_t addr) {
    asm volatile("ldmatrix.sync.aligned.m8n8.x4.shared.b16 {%0,%1,%2,%3}, [%4];"
        : "=r"(r[0]), "=r"(r[1]), "=r"(r[2]), "=r"(r[3]) : "r"(addr));
}
__device__ __forceinline__ void mma16816(float (&c)[4], const uint32_t (&a)[4],
                                         uint32_t b0, uint32_t b1) {
    asm volatile("mma.sync.aligned.m16n8k16.row.col.f32.f16.f16.f32 "
        "{%0,%1,%2,%3}, {%4,%5,%6,%7}, {%8,%9}, {%0,%1,%2,%3};"
        : "+f"(c[0]), "+f"(c[1]), "+f"(c[2]), "+f"(c[3])
        : "r"(a[0]), "r"(a[1]), "r"(a[2]), "r"(a[3]), "r"(b0), "r"(b1));
}

// ---------------------- GEMM core -------------------------------------------
// C[128 x 128] = A[rowTile..+128][:K] * B[colTile..+128][:K]^T
// A,B row-major fp16, row stride K. BK=64 (128B rows, XOR-swizzled), 3 stages.
// 8 warps, warp grid 4(M) x 2(N), warp tile 32x64 via 2x8 m16n8k16.
#define STAGES 3
#define TILEB  (128*128)              // 16384 B per tile
#define STAGEB (2*TILEB)              // 32768 B (A + B)
#define SMEMB  (STAGES*STAGEB)        // 98304 B

// physical smem offset for (row, 16B-seg) with bank swizzle
#define SWZ(row, seg) ((row) * 128 + ((((seg) ^ ((row) & 7))) << 4))

__device__ __forceinline__ void gemm_mma(
    const __half* A, const __half* B,
    int K, size_t rowTile, size_t colTile, uint32_t sbase, float acc[2][8][4])
{
    const int tid  = threadIdx.x;
    const int lane = tid & 31;
    const int warp = tid >> 5;
    const int wm = warp & 3;          // M offset wm*32
    const int wn = warp >> 2;         // N offset wn*64
    const int NIT = K >> 6;           // 64-wide k chunks

#pragma unroll
    for (int im = 0; im < 2; im++)
#pragma unroll
        for (int in = 0; in < 8; in++)
#pragma unroll
            for (int j = 0; j < 4; j++) acc[im][in][j] = 0.f;

    auto issue = [&](int j) {
        int kb = j << 6;
        uint32_t sA = sbase + (j % STAGES) * STAGEB;
        uint32_t sB = sA + TILEB;
#pragma unroll
        for (int i = 0; i < 4; i++) {
            int c = tid + 256 * i;            // 0..1023
            int row = c >> 3, seg = c & 7;
            cp_async16(sA + SWZ(row, seg),
                       A + (rowTile + row) * (size_t)K + kb + seg * 8);
        }
#pragma unroll
        for (int i = 0; i < 4; i++) {
            int c = tid + 256 * i;
            int row = c >> 3, seg = c & 7;
            cp_async16(sB + SWZ(row, seg),
                       B + (colTile + row) * (size_t)K + kb + seg * 8);
        }
        CP_COMMIT();
    };

    issue(0); issue(1);

    // ldmatrix lane decomposition (g = lane>>3)
    const uint32_t rm    = lane & 7;
    const uint32_t aRow0 = (uint32_t)(wm * 32 + ((lane >> 3) & 1) * 8 + rm) * 128;
    const uint32_t aColg = (uint32_t)(lane >> 4);          // g>>1
    const uint32_t bRow0 = (uint32_t)(wn * 64 + (lane >> 4) * 8 + rm) * 128;
    const uint32_t bColg = (uint32_t)((lane >> 3) & 1);    // g&1

    for (int it = 0; it < NIT; it++) {
        if (it + 1 < NIT) asm volatile("cp.async.wait_group 1;" ::: "memory");
        else              asm volatile("cp.async.wait_group 0;" ::: "memory");
        __syncthreads();
        if (it + 2 < NIT) issue(it + 2);

        uint32_t sA = sbase + (it % STAGES) * STAGEB;
        uint32_t sB = sA + TILEB;
#pragma unroll
        for (int ks = 0; ks < 4; ks++) {       // four k16 steps per 64-chunk
            uint32_t aC = (((uint32_t)(ks * 2) + aColg) ^ rm) << 4;
            uint32_t bC = (((uint32_t)(ks * 2) + bColg) ^ rm) << 4;
            uint32_t a0[4], a1[4], b[4][4];
            ldsm4(a0, sA + aRow0 + aC);
            ldsm4(a1, sA + aRow0 + 16 * 128 + aC);
#pragma unroll
            for (int inp = 0; inp < 4; inp++)
                ldsm4(b[inp], sB + bRow0 + inp * 16 * 128 + bC);
#pragma unroll
            for (int inp = 0; inp < 4; inp++) {
                mma16816(acc[0][inp * 2 + 0], a0, b[inp][0], b[inp][1]);
                mma16816(acc[1][inp * 2 + 0], a1, b[inp][0], b[inp][1]);
                mma16816(acc[0][inp * 2 + 1], a0, b[inp][2], b[inp][3]);
                mma16816(acc[1][inp * 2 + 1], a1, b[inp][2], b[inp][3]);
            }
        }
    }
}

// ---------------------- merged projection kernel (1-pass, hi-only) ----------
// z=0: q = tau_q * x_h·W_q_hi  (store hi at [n][d])
// z=1: k = tau_k * x_h·W_k_hi  (store hi at [n][d])
// z=2: v = tau_v * W_v_hi·x_h  (store hi transposed at [b][e][m])
__global__ __launch_bounds__(256, 2) void k_proj(const float* __restrict__ tq,
                                                 const float* __restrict__ tk,
                                                 const float* __restrict__ tv)
{
    extern __shared__ char dsm[];
    uint32_t sbase = smem_u32(dsm);
    int z = blockIdx.z;
    size_t woff = (size_t)z * DDIM * DDIM;
    float acc[2][8][4];
    int lane = threadIdx.x & 31, warp = threadIdx.x >> 5;
    int wm = warp & 3, wn = warp >> 2;

    if (z == 2) {
        size_t rowTile = (size_t)blockIdx.x * 128;   // e (8 tiles)
        size_t colTile = (size_t)blockIdx.y * 128;   // flat n (128 tiles)
        gemm_mma(g_wth + woff, g_xh, DDIM, rowTile, colTile, sbase, acc);

        float tau = tv[0];
#pragma unroll
        for (int im = 0; im < 2; im++)
#pragma unroll
            for (int in = 0; in < 8; in++) {
                size_t e0 = rowTile + wm * 32 + im * 16 + (lane >> 2);
                size_t nf = colTile + wn * 64 + in * 8 + (lane & 3) * 2;
                size_t b = nf >> 11, m = nf & (NSEQ - 1);
#pragma unroll
                for (int h = 0; h < 2; h++) {
                    size_t e = e0 + h * 8;
                    __half2 hv;
                    hv.x = __float2half_rn(acc[im][in][2 * h + 0] * tau);
                    hv.y = __float2half_rn(acc[im][in][2 * h + 1] * tau);
                    *(__half2*)&g_vth[(b * DDIM + e) * NSEQ + m] = hv;
                }
            }
    } else {
        size_t rowTile = (size_t)blockIdx.y * 128;   // flat n
        size_t colTile = (size_t)blockIdx.x * 128;   // d
        gemm_mma(g_xh, g_wth + woff, DDIM, rowTile, colTile, sbase, acc);

        float tau = z ? tk[0] : tq[0];
        __half* O = z ? g_kh : g_qh;
#pragma unroll
        for (int im = 0; im < 2; im++)
#pragma unroll
            for (int in = 0; in < 8; in++) {
                size_t n0 = rowTile + wm * 32 + im * 16 + (lane >> 2);
                size_t d  = colTile + wn * 64 + in * 8 + (lane & 3) * 2;
#pragma unroll
                for (int h = 0; h < 2; h++) {
                    size_t n = n0 + h * 8;
                    __half2 hv;
                    hv.x = __float2half_rn(acc[im][in][2 * h + 0] * tau);
                    hv.y = __float2half_rn(acc[im][in][2 * h + 1] * tau);
                    *(__half2*)&O[n * DDIM + d] = hv;
                }
            }
    }
}

// ---------------------- kernel: scores (1-pass) -----------------------------
// C[n][m] = q_h[n]·k_h[m];  S[b][n][m] = C*scale + P[n][m] + c[(n-m)&4095]
__global__ __launch_bounds__(256, 2) void k_scores(const float* __restrict__ P)
{
    extern __shared__ char dsm[];
    uint32_t sbase = smem_u32(dsm);
    int b = blockIdx.z;
    size_t rowTile = (size_t)b * NSEQ + blockIdx.y * 128;   // flat n into q
    size_t colTile = (size_t)b * NSEQ + blockIdx.x * 128;   // flat m into k

    float acc[2][8][4];
    gemm_mma(g_qh, g_kh, DDIM, rowTile, colTile, sbase, acc);

    const float scale = 0.03125f;
    float* S = g_s + (size_t)b * NSEQ * NSEQ;
    int lane = threadIdx.x & 31, warp = threadIdx.x >> 5;
    int wm = warp & 3, wn = warp >> 2;
#pragma unroll
    for (int im = 0; im < 2; im++)
#pragma unroll
        for (int in = 0; in < 8; in++) {
            int n0 = blockIdx.y * 128 + wm * 32 + im * 16 + (lane >> 2);
            int m  = blockIdx.x * 128 + wn * 64 + in * 8 + (lane & 3) * 2;
#pragma unroll
            for (int h = 0; h < 2; h++) {
                int n = n0 + h * 8;
                float2 pv = *(const float2*)&P[(size_t)n * NSEQ + m];
                float2 v;
                v.x = acc[im][in][2 * h + 0] * scale + pv.x + g_c[(n - m) & (TWO_N - 1)];
                v.y = acc[im][in][2 * h + 1] * scale + pv.y + g_c[(n - m - 1) & (TWO_N - 1)];
                *(float2*)&S[(size_t)n * NSEQ + m] = v;
            }
        }
}

// ---------------------- kernel: out = A_h @ v_h (1-pass) --------------------
__global__ __launch_bounds__(256, 2) void k_out(float* __restrict__ O)
{
    extern __shared__ char dsm[];
    uint32_t sbase = smem_u32(dsm);
    int b = blockIdx.z;
    size_t rowTile = (size_t)b * NSEQ + blockIdx.y * 128;   // flat n into attn
    size_t colTile = (size_t)b * DDIM + blockIdx.x * 128;   // flat e into vT

    float acc[2][8][4];
    gemm_mma(g_ah, g_vth, NSEQ, rowTile, colTile, sbase, acc);

    int lane = threadIdx.x & 31, warp = threadIdx.x >> 5;
    int wm = warp & 3, wn = warp >> 2;
#pragma unroll
    for (int im = 0; im < 2; im++)
#pragma unroll
        for (int in = 0; in < 8; in++) {
            int n0 = blockIdx.y * 128 + wm * 32 + im * 16 + (lane >> 2);
            int e  = blockIdx.x * 128 + wn * 64 + in * 8 + (lane & 3) * 2;
#pragma unroll
            for (int h = 0; h < 2; h++) {
                int n = n0 + h * 8;
                float2 v = make_float2(acc[im][in][2 * h + 0], acc[im][in][2 * h + 1]);
                *(float2*)&O[((size_t)b * NSEQ + n) * DDIM + e] = v;
            }
        }
}

// ---------------------- merged prologue kernel ------------------------------
// blocks [0, NBX)            : x -> fp16 convert
// blocks [NBX, NBX+NBW)      : W transpose (hi only)
// blocks [NBX+NBW, +TWO_N)   : circulant bias column
#define NBX ((MTOT*DDIM)/1024)        // 16384
#define NBW (32*32*3)                 // 3072

__global__ __launch_bounds__(256) void k_prologue(
    const float* __restrict__ x,
    const float* __restrict__ Wq, const float* __restrict__ Wk,
    const float* __restrict__ Wv, const float* __restrict__ R)
{
    int blk = blockIdx.x;
    int tid = threadIdx.x;

    if (blk < NBX) {                         // ---- conv_x ----
        size_t i = (size_t)blk * 256 + tid;
        float4 v = ((const float4*)x)[i];
        __half2 h01, h23;
        h01.x = __float2half_rn(v.x); h01.y = __float2half_rn(v.y);
        h23.x = __float2half_rn(v.z); h23.y = __float2half_rn(v.w);
        *(__half2*)&g_xh[i * 4 + 0] = h01;
        *(__half2*)&g_xh[i * 4 + 2] = h23;
    } else if (blk < NBX + NBW) {            // ---- conv_wT ----
        int idx = blk - NBX;
        int z = idx / (32 * 32);
        int rem = idx % (32 * 32);
        const float* W = (z == 0) ? Wq : (z == 1) ? Wk : Wv;
        int bx = (rem % 32) * 32, by = (rem / 32) * 32;
        int tx = tid & 31, ty = tid >> 5;    // 32 x 8
        __shared__ float t[32][33];
#pragma unroll
        for (int i = 0; i < 4; i++)
            t[ty + i * 8][tx] = W[(size_t)(by + ty + i * 8) * DDIM + bx + tx];
        __syncthreads();
        size_t base = (size_t)z * DDIM * DDIM;
#pragma unroll
        for (int i = 0; i < 4; i++) {
            int d = bx + ty + i * 8, k = by + tx;
            g_wth[base + (size_t)d * DDIM + k] = __float2half_rn(t[tx][ty + i * 8]);
        }
    } else {                                 // ---- bias ----
        int t = blk - NBX - NBW;
        int lane = tid & 31, wid = tid >> 5;
        __shared__ float red[8];
        const float w = 6.283185307179586f / (float)TWO_N;
        float s = 0.f;
        for (int j = tid; j < TWO_N; j += 256)
            s += R[j] * cosf(w * (float)((j * t) & (TWO_N - 1)));
#pragma unroll
        for (int o = 16; o; o >>= 1) s += __shfl_xor_sync(0xFFFFFFFFu, s, o);
        if (lane == 0) red[wid] = s;
        __syncthreads();
        if (tid == 0) {
            float tot = 0.f;
#pragma unroll
            for (int i = 0; i < 8; i++) tot += red[i];
            g_c[t] = tot * (1.0f / (float)TWO_N);
        }
    }
}

// ---------------------- softmax (hi-only store) -----------------------------
__global__ __launch_bounds__(256) void softmax_kernel() {
    size_t row = blockIdx.x;
    float* p = g_s + row * NSEQ;
    __half* ah = g_ah + row * NSEQ;
    int t = threadIdx.x, lane = t & 31, wid = t >> 5;
    __shared__ float red[8];

    float x[8];
#pragma unroll
    for (int i = 0; i < 8; i++) x[i] = p[t + i * 256];
    float m = x[0];
#pragma unroll
    for (int i = 1; i < 8; i++) m = fmaxf(m, x[i]);
#pragma unroll
    for (int o = 16; o; o >>= 1) m = fmaxf(m, __shfl_xor_sync(0xFFFFFFFFu, m, o));
    if (lane == 0) red[wid] = m;
    __syncthreads();
    float bm = red[0];
#pragma unroll
    for (int i = 1; i < 8; i++) bm = fmaxf(bm, red[i]);
    __syncthreads();
    float s = 0.f;
#pragma unroll
    for (int i = 0; i < 8; i++) { x[i] = expf(x[i] - bm); s += x[i]; }
#pragma unroll
    for (int o = 16; o; o >>= 1) s += __shfl_xor_sync(0xFFFFFFFFu, s, o);
    if (lane == 0) red[wid] = s;
    __syncthreads();
    float tot = red[0];
#pragma unroll
    for (int i = 1; i < 8; i++) tot += red[i];
    float inv = 1.0f / tot;
#pragma unroll
    for (int i = 0; i < 8; i++)
        ah[t + i * 256] = __float2half_rn(x[i] * inv);
}

// ---------------------- launch ----------------------------------------------
extern "C" void kernel_launch(void* const* d_in, const int* in_sizes, int n_in,
                              void* d_out, int out_size)
{
    const float* x  = (const float*)d_in[0];
    const float* Wq = (const float*)d_in[1];
    const float* Wk = (const float*)d_in[2];
    const float* Wv = (const float*)d_in[3];
    const float* P  = (const float*)d_in[4];
    const float* R  = (const float*)d_in[5];
    const float* tq = (const float*)d_in[6];
    const float* tk = (const float*)d_in[7];
    const float* tv = (const float*)d_in[8];
    float* out = (float*)d_out;

    cudaFuncSetAttribute(k_proj,   cudaFuncAttributeMaxDynamicSharedMemorySize, SMEMB);
    cudaFuncSetAttribute(k_scores, cudaFuncAttributeMaxDynamicSharedMemorySize, SMEMB);
    cudaFuncSetAttribute(k_out,    cudaFuncAttributeMaxDynamicSharedMemorySize, SMEMB);

    k_prologue<<<NBX + NBW + TWO_N, 256>>>(x, Wq, Wk, Wv, R);
    {
        dim3 gProjQK(DDIM / 128, MTOT / 128, 2);
        (void)gProjQK;
    }
    k_proj  <<<dim3(DDIM / 128, MTOT / 128, 3), 256, SMEMB>>>(tq, tk, tv);
    k_scores<<<dim3(NSEQ / 128, NSEQ / 128, BATCH), 256, SMEMB>>>(P);
    softmax_kernel<<<dim3(BATCH * NSEQ), 256>>>();
    k_out   <<<dim3(DDIM / 128, NSEQ / 128, BATCH), 256, SMEMB>>>(out);
}